// round 1
// baseline (speedup 1.0000x reference)
#include <cuda_runtime.h>
#include <cuda_bf16.h>
#include <cstdint>

// Problem constants
constexpr int NB  = 2;    // batch
constexpr int NN  = 768;  // nodes
constexpr int NU  = 64;   // embed dim
constexpr int NK  = 8;    // relation dim
constexpr int NIN = 136;  // 2U + K
constexpr int NPAD = 160; // padded neuron count (5 per lane * 32 lanes)
constexpr float SLOPE = 0.01f;

// ---------------- device scratch (no allocations allowed) ----------------
__device__ unsigned char g_mask[NN * NN];
__device__ int   g_Dint[NN];
__device__ float g_invD[NN];
__device__ int   g_colrows[NN * NN];
__device__ int   g_colcnt[NN];
__device__ float g_x1[NB * NN * NU];

// ---------------- kernel 1: zero degree counters ----------------
__global__ void zero_D_kernel() {
    int i = threadIdx.x;
    if (i < NN) g_Dint[i] = 0;
}

// ---------------- kernel 2: mask + row degrees ----------------
__global__ void mask_kernel(const float* __restrict__ rel) {
    int idx = blockIdx.x * blockDim.x + threadIdx.x;
    if (idx >= NN * NN) return;
    const float4* p = reinterpret_cast<const float4*>(rel + (size_t)idx * NK);
    float4 a = p[0], b = p[1];
    float s = a.x + a.y + a.z + a.w + b.x + b.y + b.z + b.w;
    unsigned char m = (s > 0.0f) ? 1 : 0;
    g_mask[idx] = m;
    if (m) atomicAdd(&g_Dint[idx / NN], 1);
}

// ---------------- kernel 3: deterministic per-column edge lists ----------------
__global__ void build_cols_kernel() {
    __shared__ unsigned char flags[NN];
    int j = blockIdx.x;
    for (int i = threadIdx.x; i < NN; i += blockDim.x)
        flags[i] = g_mask[i * NN + j];
    __syncthreads();
    if (threadIdx.x == 0) {
        int cnt = 0;
        for (int i = 0; i < NN; i++)
            if (flags[i]) g_colrows[j * NN + cnt++] = i;
        g_colcnt[j] = cnt;
    }
}

// ---------------- kernel 4: 1/D ----------------
__global__ void invd_kernel() {
    int i = threadIdx.x;
    if (i < NN) {
        int d = g_Dint[i];
        g_invD[i] = 1.0f / (float)(d > 0 ? d : 1);
    }
}

// ---------------- hop kernel ----------------
// smem layout (floats)
constexpr int OFF_W1 = 0;                        // 136 * 160
constexpr int OFF_B1 = OFF_W1 + NIN * NPAD;      // 160
constexpr int OFF_W2 = OFF_B1 + NPAD;            // 160
constexpr int OFF_C  = OFF_W2 + NPAD;            // 8 warps * 4 edges * 136 (interleaved)
constexpr int OFF_P  = OFF_C + 8 * 4 * NIN;      // 8 warp partials + 1 total
constexpr int SMEM_FLOATS = OFF_P + 9;
constexpr int SMEM_BYTES  = SMEM_FLOATS * 4;     // 105,764 B

__global__ void __launch_bounds__(256, 2) hop_kernel(
    const float* __restrict__ xin_ext,   // external input (hop 1) or nullptr
    float* __restrict__ xout_ext,        // external output (hop 2) or nullptr
    int use_g_in, int use_g_out,
    const float* __restrict__ rel,
    const float* __restrict__ W1,        // (136,136) row-major (in,out)
    const float* __restrict__ b1,        // (136)
    const float* __restrict__ w2,        // (136)   second linear weights
    const float* __restrict__ b2p)       // (1)     second linear bias
{
    extern __shared__ float sm[];
    float* sW1   = sm + OFF_W1;
    float* sb1   = sm + OFF_B1;
    float* sw2   = sm + OFF_W2;
    float* sc    = sm + OFF_C;
    float* spart = sm + OFF_P;

    const float* xin  = use_g_in  ? g_x1 : xin_ext;
    float*       xout = use_g_out ? g_x1 : xout_ext;

    int tid = threadIdx.x;

    // load W1 into smem, zero-padded to 160 output neurons
    for (int idx = tid; idx < NIN * NPAD; idx += blockDim.x) {
        int k = idx / NPAD, n = idx % NPAD;
        sW1[idx] = (n < NIN) ? W1[k * NIN + n] : 0.0f;
    }
    if (tid < NPAD) {
        sb1[tid] = (tid < NIN) ? b1[tid] : 0.0f;
        sw2[tid] = (tid < NIN) ? w2[tid] : 0.0f;
    }
    float b2 = *b2p;
    __syncthreads();

    int warp = tid >> 5, lane = tid & 31;
    float* myc = sc + warp * (4 * NIN);   // interleaved: myc[k*4 + s]

    // persistent loop over (b, j) pairs
    for (int p = blockIdx.x; p < NB * NN; p += gridDim.x) {
        int b = p / NN, j = p % NN;
        int cnt = g_colcnt[j];
        const float* xb = xin + (size_t)b * NN * NU;
        float wacc = 0.0f;

        int nG = (cnt + 3) >> 2;                 // groups of 4 edges
        for (int G = warp; G < nG; G += 8) {
            int e0 = G << 2;
            int  iv[4];
            bool valid[4];
            // build 4 activation vectors c = [x_i ; x_j ; rel_ij], interleaved by edge
            #pragma unroll
            for (int s = 0; s < 4; s++) {
                int e = e0 + s;
                bool v = (e < cnt);
                int i = g_colrows[j * NN + (v ? e : 0)];
                iv[s] = i;
                valid[s] = v;
                const float* xi = xb + i * NU;
                const float* xj = xb + j * NU;
                myc[(lane      ) * 4 + s] = xi[lane];
                myc[(lane +  32) * 4 + s] = xi[lane + 32];
                myc[(lane +  64) * 4 + s] = xj[lane];
                myc[(lane +  96) * 4 + s] = xj[lane + 32];
                if (lane < 8)
                    myc[(lane + 128) * 4 + s] = rel[((size_t)i * NN + j) * NK + lane];
            }
            __syncwarp();

            // h[s][m]: neuron n = lane + 32*m for edge s
            float h[4][5];
            #pragma unroll
            for (int s = 0; s < 4; s++)
                #pragma unroll
                for (int m = 0; m < 5; m++)
                    h[s][m] = sb1[lane + 32 * m];

            #pragma unroll 4
            for (int k = 0; k < NIN; k++) {
                float4 cv = *reinterpret_cast<const float4*>(myc + 4 * k); // broadcast
                float c[4] = {cv.x, cv.y, cv.z, cv.w};
                float w1v[5];
                #pragma unroll
                for (int m = 0; m < 5; m++)
                    w1v[m] = sW1[k * NPAD + lane + 32 * m];
                #pragma unroll
                for (int s = 0; s < 4; s++)
                    #pragma unroll
                    for (int m = 0; m < 5; m++)
                        h[s][m] = fmaf(c[s], w1v[m], h[s][m]);
            }

            // epilogue: leaky, dot with w2, warp-reduce, leaky, accumulate /D[i]
            #pragma unroll
            for (int s = 0; s < 4; s++) {
                float dot = 0.0f;
                #pragma unroll
                for (int m = 0; m < 5; m++) {
                    float hv = h[s][m];
                    hv = hv > 0.0f ? hv : SLOPE * hv;
                    dot += hv * sw2[lane + 32 * m];
                }
                #pragma unroll
                for (int off = 16; off > 0; off >>= 1)
                    dot += __shfl_xor_sync(0xffffffffu, dot, off);
                float o = dot + b2;
                o = o > 0.0f ? o : SLOPE * o;
                if (valid[s]) wacc += o * g_invD[iv[s]];
            }
            __syncwarp();
        }

        if (lane == 0) spart[warp] = wacc;
        __syncthreads();
        if (tid == 0) {
            float S = 0.0f;
            #pragma unroll
            for (int w = 0; w < 8; w++) S += spart[w];
            spart[8] = S;
        }
        __syncthreads();
        if (tid < NU) {
            float S = spart[8];
            xout[(size_t)p * NU + tid] = xb[j * NU + tid] * S;
        }
        __syncthreads();   // protect spart before next pair
    }
}

// ---------------- launch ----------------
extern "C" void kernel_launch(void* const* d_in, const int* in_sizes, int n_in,
                              void* d_out, int out_size) {
    const float* seq  = (const float*)d_in[0];
    const float* rel  = (const float*)d_in[1];
    const float* w1_1 = (const float*)d_in[2];
    const float* b1_1 = (const float*)d_in[3];
    const float* w1_2 = (const float*)d_in[4];
    const float* b1_2 = (const float*)d_in[5];
    const float* w2_1 = (const float*)d_in[6];
    const float* b2_1 = (const float*)d_in[7];
    const float* w2_2 = (const float*)d_in[8];
    const float* b2_2 = (const float*)d_in[9];
    float* out = (float*)d_out;

    cudaFuncSetAttribute(hop_kernel,
                         cudaFuncAttributeMaxDynamicSharedMemorySize, SMEM_BYTES);

    zero_D_kernel<<<1, NN>>>();
    mask_kernel<<<(NN * NN + 255) / 256, 256>>>(rel);
    build_cols_kernel<<<NN, 256>>>();
    invd_kernel<<<1, NN>>>();

    const int GRID = 304; // 2 blocks/SM persistent (152 SMs on GB300)
    // hop 1: seq -> g_x1
    hop_kernel<<<GRID, 256, SMEM_BYTES>>>(seq, nullptr, 0, 1, rel,
                                          w1_1, b1_1, w1_2, b1_2);
    // hop 2: g_x1 -> out
    hop_kernel<<<GRID, 256, SMEM_BYTES>>>(nullptr, out, 1, 0, rel,
                                          w2_1, b2_1, w2_2, b2_2);
}

// round 2
// speedup vs baseline: 2.5975x; 2.5975x over previous
#include <cuda_runtime.h>
#include <cuda_bf16.h>
#include <cstdint>

// Problem constants
constexpr int NB  = 2;    // batch
constexpr int NN  = 768;  // nodes
constexpr int NU  = 64;   // embed dim
constexpr int NK  = 8;    // relation dim
constexpr int NIN = 136;  // 2U + K
constexpr int NPD = 160;  // padded hidden (5 per lane * 32 lanes)
constexpr float SLOPE = 0.01f;

// ---------------- device scratch (no allocations allowed) ----------------
__device__ unsigned char g_mask[NN * NN];
__device__ float g_invD[NN];
__device__ int   g_colrows[NN * NN];
__device__ int   g_colcnt[NN];
__device__ float g_A   [NB * NN * NPD];   // per-node W1a @ x_i
__device__ float g_Base[NB * NN * NPD];   // per-node W1b @ x_j + b1
__device__ float g_x1  [NB * NN * NU];    // hop-1 output

// ---------------- kernel 1: mask + row degree + invD (fused) ----------------
__global__ void maskdeg_kernel(const float* __restrict__ rel) {
    int i = blockIdx.x;
    int tid = threadIdx.x;
    int cnt = 0;
    for (int j = tid; j < NN; j += 256) {
        const float4* p = reinterpret_cast<const float4*>(rel + ((size_t)i * NN + j) * NK);
        float4 a = p[0], b = p[1];
        float s = a.x + a.y + a.z + a.w + b.x + b.y + b.z + b.w;
        unsigned char m = (s > 0.0f) ? 1 : 0;
        g_mask[i * NN + j] = m;
        cnt += m;
    }
    #pragma unroll
    for (int o = 16; o > 0; o >>= 1) cnt += __shfl_xor_sync(~0u, cnt, o);
    __shared__ int wsum[8];
    if ((tid & 31) == 0) wsum[tid >> 5] = cnt;
    __syncthreads();
    if (tid == 0) {
        int t = 0;
        #pragma unroll
        for (int w = 0; w < 8; w++) t += wsum[w];
        g_invD[i] = 1.0f / (float)(t > 0 ? t : 1);
    }
}

// ---------------- kernel 2: per-column edge lists via ballot scan ----------------
__global__ void build_cols_kernel() {
    int j = blockIdx.x;
    int tid = threadIdx.x;          // 0..767, tid == row i
    int warp = tid >> 5, lane = tid & 31;
    int flag = g_mask[tid * NN + j];
    unsigned bal = __ballot_sync(~0u, flag != 0);
    __shared__ int wcnt[24];
    __shared__ int wpre[25];
    if (lane == 0) wcnt[warp] = __popc(bal);
    __syncthreads();
    if (tid == 0) {
        int acc = 0;
        #pragma unroll
        for (int w = 0; w < 24; w++) { wpre[w] = acc; acc += wcnt[w]; }
        wpre[24] = acc;
        g_colcnt[j] = acc;
    }
    __syncthreads();
    if (flag) {
        int pos = wpre[warp] + __popc(bal & ((1u << lane) - 1u));
        g_colrows[j * NN + pos] = tid;
    }
}

// ---------------- kernel 3: per-node precompute A, Base ----------------
constexpr int RPB = 8;  // rows per block
__global__ void precompute_kernel(const float* __restrict__ xext, int use_g,
                                  const float* __restrict__ W1,
                                  const float* __restrict__ b1) {
    const float* xp = use_g ? g_x1 : xext;
    __shared__ float sx[RPB][NU];
    int R0 = blockIdx.x * RPB;
    int tid = threadIdx.x;          // 0..159
    for (int idx = tid; idx < RPB * NU; idx += 160)
        sx[idx >> 6][idx & 63] = xp[(size_t)R0 * NU + idx];
    __syncthreads();
    int n = tid;
    float a[RPB], bs[RPB];
    #pragma unroll
    for (int r = 0; r < RPB; r++) { a[r] = 0.0f; bs[r] = 0.0f; }
    if (n < NIN) {
        #pragma unroll 4
        for (int u = 0; u < NU; u++) {
            float wa = W1[u * NIN + n];
            float wb = W1[(NU + u) * NIN + n];
            #pragma unroll
            for (int r = 0; r < RPB; r++) {
                a[r]  = fmaf(sx[r][u], wa, a[r]);
                bs[r] = fmaf(sx[r][u], wb, bs[r]);
            }
        }
        float bb = b1[n];
        #pragma unroll
        for (int r = 0; r < RPB; r++) {
            g_A   [(size_t)(R0 + r) * NPD + n] = a[r];
            g_Base[(size_t)(R0 + r) * NPD + n] = bs[r] + bb;
        }
    } else {
        #pragma unroll
        for (int r = 0; r < RPB; r++) {
            g_A   [(size_t)(R0 + r) * NPD + n] = 0.0f;
            g_Base[(size_t)(R0 + r) * NPD + n] = 0.0f;
        }
    }
}

// ---------------- kernel 4: edge phase ----------------
// Each block handles exactly 3 (b,j) pairs (512*3 = 1536). 8 warps split edges.
// Per edge: h[n] = A[b,i,n] + Base[b,j,n] + rel_ij @ W1c, then leaky -> dot(w2)
// -> reduce -> leaky -> * invD[i]. W1c and w2 live entirely in registers.
__global__ void __launch_bounds__(256) edge_kernel(
    const float* __restrict__ xin_ext, float* __restrict__ xout_ext,
    int use_g_in, int use_g_out,
    const float* __restrict__ rel,
    const float* __restrict__ W1,      // full (136,136); we read rows 128..135
    const float* __restrict__ w2,      // (136,1)
    const float* __restrict__ b2p)     // (1,)
{
    const float* xin  = use_g_in  ? g_x1 : xin_ext;
    float*       xout = use_g_out ? g_x1 : xout_ext;

    int tid = threadIdx.x, warp = tid >> 5, lane = tid & 31;

    // per-lane weights in registers (zero-padded neurons)
    float w1c[NK][5], w2v[5];
    #pragma unroll
    for (int m = 0; m < 5; m++) {
        int n = lane + 32 * m;
        w2v[m] = (n < NIN) ? w2[n] : 0.0f;
        #pragma unroll
        for (int kk = 0; kk < NK; kk++)
            w1c[kk][m] = (n < NIN) ? W1[(2 * NU + kk) * NIN + n] : 0.0f;
    }
    float b2 = __ldg(b2p);

    __shared__ float spart[9];

    for (int p = blockIdx.x; p < NB * NN; p += gridDim.x) {
        int b = p / NN, j = p % NN;
        int cnt = g_colcnt[j];
        const int* rows = g_colrows + j * NN;
        const float* Bs = g_Base + (size_t)p * NPD;
        float base[5];
        #pragma unroll
        for (int m = 0; m < 5; m++) base[m] = Bs[lane + 32 * m];

        float wacc = 0.0f;
        for (int e = warp; e < cnt; e += 8) {
            int i = rows[e];
            const float* Ar = g_A + (size_t)(b * NN + i) * NPD;
            float h[5];
            #pragma unroll
            for (int m = 0; m < 5; m++) h[m] = Ar[lane + 32 * m] + base[m];

            const float4* rp = reinterpret_cast<const float4*>(rel + ((size_t)i * NN + j) * NK);
            float4 r0 = rp[0], r1 = rp[1];
            float rv[8] = {r0.x, r0.y, r0.z, r0.w, r1.x, r1.y, r1.z, r1.w};
            #pragma unroll
            for (int kk = 0; kk < NK; kk++)
                #pragma unroll
                for (int m = 0; m < 5; m++)
                    h[m] = fmaf(rv[kk], w1c[kk][m], h[m]);

            float d = 0.0f;
            #pragma unroll
            for (int m = 0; m < 5; m++) {
                float hv = fmaxf(h[m], SLOPE * h[m]);   // leaky_relu
                d = fmaf(hv, w2v[m], d);
            }
            #pragma unroll
            for (int o = 16; o > 0; o >>= 1) d += __shfl_xor_sync(~0u, d, o);
            float o2 = d + b2;
            o2 = fmaxf(o2, SLOPE * o2);
            wacc += o2 * g_invD[i];
        }

        if (lane == 0) spart[warp] = wacc;
        __syncthreads();
        if (tid == 0) {
            float S = 0.0f;
            #pragma unroll
            for (int w = 0; w < 8; w++) S += spart[w];
            spart[8] = S;
        }
        __syncthreads();
        if (tid < NU)
            xout[(size_t)p * NU + tid] = xin[(size_t)p * NU + tid] * spart[8];
        __syncthreads();
    }
}

// ---------------- launch ----------------
extern "C" void kernel_launch(void* const* d_in, const int* in_sizes, int n_in,
                              void* d_out, int out_size) {
    const float* seq  = (const float*)d_in[0];
    const float* rel  = (const float*)d_in[1];
    const float* w1_1 = (const float*)d_in[2];
    const float* b1_1 = (const float*)d_in[3];
    const float* w1_2 = (const float*)d_in[4];
    const float* b1_2 = (const float*)d_in[5];
    const float* w2_1 = (const float*)d_in[6];
    const float* b2_1 = (const float*)d_in[7];
    const float* w2_2 = (const float*)d_in[8];
    const float* b2_2 = (const float*)d_in[9];
    float* out = (float*)d_out;

    maskdeg_kernel   <<<NN, 256>>>(rel);
    build_cols_kernel<<<NN, 768>>>();

    // hop 1: seq -> g_x1
    precompute_kernel<<<NB * NN / RPB, 160>>>(seq, 0, w1_1, b1_1);
    edge_kernel      <<<512, 256>>>(seq, nullptr, 0, 1, rel, w1_1, w1_2, b1_2);

    // hop 2: g_x1 -> out
    precompute_kernel<<<NB * NN / RPB, 160>>>(nullptr, 1, w2_1, b2_1);
    edge_kernel      <<<512, 256>>>(nullptr, out, 1, 0, rel, w2_1, w2_2, b2_2);
}

// round 3
// speedup vs baseline: 2.9770x; 1.1461x over previous
#include <cuda_runtime.h>
#include <cuda_bf16.h>
#include <cstdint>

// Problem constants
constexpr int NB  = 2;    // batch
constexpr int NN  = 768;  // nodes
constexpr int NU  = 64;   // embed dim
constexpr int NK  = 8;    // relation dim
constexpr int NIN = 136;  // 2U + K
constexpr int NPD = 160;  // padded hidden (5 per lane * 32 lanes)
constexpr float SLOPE = 0.01f;

// ---------------- device scratch ----------------
__device__ unsigned char g_mask[NN * NN];
__device__ float g_invD[NN];
__device__ int   g_colrows[NN * NN];
__device__ int   g_colcnt[NN];
__device__ float g_A   [NB * NN * NPD];
__device__ float g_Base[NB * NN * NPD];
__device__ float g_x1  [NB * NN * NU];

// ---------------- kernel 1: mask + row degree + invD ----------------
__global__ void maskdeg_kernel(const float* __restrict__ rel) {
    int i = blockIdx.x;
    int tid = threadIdx.x;
    int cnt = 0;
    for (int j = tid; j < NN; j += 256) {
        const float4* p = reinterpret_cast<const float4*>(rel + ((size_t)i * NN + j) * NK);
        float4 a = p[0], b = p[1];
        float s = a.x + a.y + a.z + a.w + b.x + b.y + b.z + b.w;
        unsigned char m = (s > 0.0f) ? 1 : 0;
        g_mask[i * NN + j] = m;
        cnt += m;
    }
    #pragma unroll
    for (int o = 16; o > 0; o >>= 1) cnt += __shfl_xor_sync(~0u, cnt, o);
    __shared__ int wsum[8];
    if ((tid & 31) == 0) wsum[tid >> 5] = cnt;
    __syncthreads();
    if (tid == 0) {
        int t = 0;
        #pragma unroll
        for (int w = 0; w < 8; w++) t += wsum[w];
        g_invD[i] = 1.0f / (float)(t > 0 ? t : 1);
    }
}

// ---------------- kernel 2: per-column edge lists (ballot scan) ----------------
__global__ void build_cols_kernel() {
    int j = blockIdx.x;
    int tid = threadIdx.x;          // row i
    int warp = tid >> 5, lane = tid & 31;
    int flag = g_mask[tid * NN + j];
    unsigned bal = __ballot_sync(~0u, flag != 0);
    __shared__ int wcnt[24];
    __shared__ int wpre[25];
    if (lane == 0) wcnt[warp] = __popc(bal);
    __syncthreads();
    if (tid == 0) {
        int acc = 0;
        #pragma unroll
        for (int w = 0; w < 24; w++) { wpre[w] = acc; acc += wcnt[w]; }
        wpre[24] = acc;
        g_colcnt[j] = acc;
    }
    __syncthreads();
    if (flag) {
        int pos = wpre[warp] + __popc(bal & ((1u << lane) - 1u));
        g_colrows[j * NN + pos] = tid;
    }
}

// ---------------- kernel 3: per-node precompute A, Base ----------------
constexpr int RPB = 8;
__global__ void precompute_kernel(const float* __restrict__ xext, int use_g,
                                  const float* __restrict__ W1,
                                  const float* __restrict__ b1) {
    const float* xp = use_g ? g_x1 : xext;
    __shared__ float sx[RPB][NU];
    int R0 = blockIdx.x * RPB;
    int tid = threadIdx.x;          // 0..159
    for (int idx = tid; idx < RPB * NU; idx += 160)
        sx[idx >> 6][idx & 63] = xp[(size_t)R0 * NU + idx];
    __syncthreads();
    int n = tid;
    float a[RPB], bs[RPB];
    #pragma unroll
    for (int r = 0; r < RPB; r++) { a[r] = 0.0f; bs[r] = 0.0f; }
    if (n < NIN) {
        #pragma unroll 4
        for (int u = 0; u < NU; u++) {
            float wa = W1[u * NIN + n];
            float wb = W1[(NU + u) * NIN + n];
            #pragma unroll
            for (int r = 0; r < RPB; r++) {
                a[r]  = fmaf(sx[r][u], wa, a[r]);
                bs[r] = fmaf(sx[r][u], wb, bs[r]);
            }
        }
        float bb = b1[n];
        #pragma unroll
        for (int r = 0; r < RPB; r++) {
            g_A   [(size_t)(R0 + r) * NPD + n] = a[r];
            g_Base[(size_t)(R0 + r) * NPD + n] = bs[r] + bb;
        }
    } else {
        #pragma unroll
        for (int r = 0; r < RPB; r++) {
            g_A   [(size_t)(R0 + r) * NPD + n] = 0.0f;
            g_Base[(size_t)(R0 + r) * NPD + n] = 0.0f;
        }
    }
}

// ---------------- kernel 4: edge phase, 4 edges per warp-iteration ----------------
__global__ void __launch_bounds__(256, 2) edge_kernel(
    const float* __restrict__ xin_ext, float* __restrict__ xout_ext,
    int use_g_in, int use_g_out,
    const float* __restrict__ rel,
    const float* __restrict__ W1,      // (136,136); rows 128..135 = rel weights
    const float* __restrict__ w2,      // (136,1)
    const float* __restrict__ b2p)     // (1,)
{
    const float* xin  = use_g_in  ? g_x1 : xin_ext;
    float*       xout = use_g_out ? g_x1 : xout_ext;

    __shared__ float sW1c[NK * NPD];
    __shared__ float spart[9];

    int tid = threadIdx.x, warp = tid >> 5, lane = tid & 31;

    // stage rel-weight slab of W1 into smem (zero-padded neurons)
    for (int idx = tid; idx < NK * NPD; idx += 256) {
        int kk = idx / NPD, n = idx % NPD;
        sW1c[idx] = (n < NIN) ? W1[(2 * NU + kk) * NIN + n] : 0.0f;
    }
    // per-lane constants
    float w2l[5];
    #pragma unroll
    for (int m = 0; m < 5; m++) {
        int n = lane + 32 * m;
        w2l[m] = (n < NIN) ? w2[n] : 0.0f;
    }
    float b2 = __ldg(b2p);
    __syncthreads();

    for (int p = blockIdx.x; p < NB * NN; p += gridDim.x) {
        int b = p / NN, j = p % NN;
        int cnt = g_colcnt[j];                // >= 1 (diagonal)
        const int* rows = g_colrows + j * NN;
        const float* Bs = g_Base + (size_t)p * NPD;
        float base[5];
        #pragma unroll
        for (int m = 0; m < 5; m++) base[m] = Bs[lane + 32 * m];

        float wacc = 0.0f;
        int nG = (cnt + 3) >> 2;
        for (int G = warp; G < nG; G += 8) {
            int e0 = G << 2;
            float h[4][5];
            float rv[4][8];
            float vs[4];
            // front-batched loads for 4 edges (MLP ~ 28)
            #pragma unroll
            for (int s = 0; s < 4; s++) {
                int e = e0 + s;
                bool v = (e < cnt);
                int i = rows[v ? e : cnt - 1];
                vs[s] = v ? g_invD[i] : 0.0f;
                const float* Ar = g_A + ((size_t)b * NN + i) * NPD;
                #pragma unroll
                for (int m = 0; m < 5; m++)
                    h[s][m] = Ar[lane + 32 * m] + base[m];
                const float4* rp = reinterpret_cast<const float4*>(
                    rel + ((size_t)i * NN + j) * NK);
                float4 r0 = rp[0], r1 = rp[1];
                rv[s][0] = r0.x; rv[s][1] = r0.y; rv[s][2] = r0.z; rv[s][3] = r0.w;
                rv[s][4] = r1.x; rv[s][5] = r1.y; rv[s][6] = r1.z; rv[s][7] = r1.w;
            }
            // rel-term MLP: 160 independent FMAs per k-step group
            #pragma unroll
            for (int kk = 0; kk < NK; kk++) {
                float w1v[5];
                #pragma unroll
                for (int m = 0; m < 5; m++)
                    w1v[m] = sW1c[kk * NPD + lane + 32 * m];
                #pragma unroll
                for (int s = 0; s < 4; s++)
                    #pragma unroll
                    for (int m = 0; m < 5; m++)
                        h[s][m] = fmaf(rv[s][kk], w1v[m], h[s][m]);
            }
            // leaky + dot with w2 (4 independent chains)
            float d[4];
            #pragma unroll
            for (int s = 0; s < 4; s++) {
                float acc = 0.0f;
                #pragma unroll
                for (int m = 0; m < 5; m++) {
                    float hv = h[s][m];
                    hv = fmaxf(hv, SLOPE * hv);
                    acc = fmaf(hv, w2l[m], acc);
                }
                d[s] = acc;
            }
            // interleaved butterfly: 4 independent shuffle chains
            #pragma unroll
            for (int o = 16; o > 0; o >>= 1) {
                #pragma unroll
                for (int s = 0; s < 4; s++)
                    d[s] += __shfl_xor_sync(~0u, d[s], o);
            }
            #pragma unroll
            for (int s = 0; s < 4; s++) {
                float o2 = d[s] + b2;
                o2 = fmaxf(o2, SLOPE * o2);
                wacc += o2 * vs[s];
            }
        }

        if (lane == 0) spart[warp] = wacc;
        __syncthreads();
        if (tid == 0) {
            float S = 0.0f;
            #pragma unroll
            for (int w = 0; w < 8; w++) S += spart[w];
            spart[8] = S;
        }
        __syncthreads();
        if (tid < NU)
            xout[(size_t)p * NU + tid] = xin[(size_t)p * NU + tid] * spart[8];
        __syncthreads();
    }
}

// ---------------- launch ----------------
extern "C" void kernel_launch(void* const* d_in, const int* in_sizes, int n_in,
                              void* d_out, int out_size) {
    const float* seq  = (const float*)d_in[0];
    const float* rel  = (const float*)d_in[1];
    const float* w1_1 = (const float*)d_in[2];
    const float* b1_1 = (const float*)d_in[3];
    const float* w1_2 = (const float*)d_in[4];
    const float* b1_2 = (const float*)d_in[5];
    const float* w2_1 = (const float*)d_in[6];
    const float* b2_1 = (const float*)d_in[7];
    const float* w2_2 = (const float*)d_in[8];
    const float* b2_2 = (const float*)d_in[9];
    float* out = (float*)d_out;

    maskdeg_kernel   <<<NN, 256>>>(rel);
    build_cols_kernel<<<NN, 768>>>();

    const int GRID = 296;  // one persistent wave at 2 blocks/SM (148 SMs)

    // hop 1: seq -> g_x1
    precompute_kernel<<<NB * NN / RPB, 160>>>(seq, 0, w1_1, b1_1);
    edge_kernel      <<<GRID, 256>>>(seq, nullptr, 0, 1, rel, w1_1, w1_2, b1_2);

    // hop 2: g_x1 -> out
    precompute_kernel<<<NB * NN / RPB, 160>>>(nullptr, 1, w2_1, b2_1);
    edge_kernel      <<<GRID, 256>>>(nullptr, out, 1, 0, rel, w2_1, w2_2, b2_2);
}

// round 4
// speedup vs baseline: 3.2545x; 1.0932x over previous
#include <cuda_runtime.h>
#include <cuda_bf16.h>
#include <cstdint>

// Problem constants
constexpr int NB  = 2;    // batch
constexpr int NN  = 768;  // nodes
constexpr int NU  = 64;   // embed dim
constexpr int NK  = 8;    // relation dim
constexpr int NIN = 136;  // 2U + K
constexpr int NPD = 160;  // padded hidden (5 per lane * 32 lanes)
constexpr int MAXE = NN * NN;
constexpr float SLOPE = 0.01f;

// ---------------- device scratch ----------------
__device__ unsigned char g_mask[NN * NN];
__device__ float g_invD[NN];
__device__ int   g_colrows[NN * NN];   // padded per-column rows (ordered by i)
__device__ int   g_colcnt[NN];
__device__ int   g_colstart[NN];
__device__ int   g_totE;
__device__ int   g_ei[MAXE];           // flat edge -> row i
__device__ int   g_ej[MAXE];           // flat edge -> col j
__device__ float g_edgeval[NB * MAXE]; // per-edge scalar contribution
__device__ float g_A   [NB * NN * NPD];
__device__ float g_Base[NB * NN * NPD];
__device__ float g_x1  [NB * NN * NU];

// ---------------- kernel 1: mask + row degree + invD ----------------
__global__ void maskdeg_kernel(const float* __restrict__ rel) {
    int i = blockIdx.x;
    int tid = threadIdx.x;
    int cnt = 0;
    for (int j = tid; j < NN; j += 256) {
        const float4* p = reinterpret_cast<const float4*>(rel + ((size_t)i * NN + j) * NK);
        float4 a = p[0], b = p[1];
        float s = a.x + a.y + a.z + a.w + b.x + b.y + b.z + b.w;
        unsigned char m = (s > 0.0f) ? 1 : 0;
        g_mask[i * NN + j] = m;
        cnt += m;
    }
    #pragma unroll
    for (int o = 16; o > 0; o >>= 1) cnt += __shfl_xor_sync(~0u, cnt, o);
    __shared__ int wsum[8];
    if ((tid & 31) == 0) wsum[tid >> 5] = cnt;
    __syncthreads();
    if (tid == 0) {
        int t = 0;
        #pragma unroll
        for (int w = 0; w < 8; w++) t += wsum[w];
        g_invD[i] = 1.0f / (float)(t > 0 ? t : 1);
    }
}

// ---------------- kernel 2: per-column edge lists (ballot scan, i-ordered) ----------------
__global__ void build_cols_kernel() {
    int j = blockIdx.x;
    int tid = threadIdx.x;          // row i
    int warp = tid >> 5, lane = tid & 31;
    int flag = g_mask[tid * NN + j];
    unsigned bal = __ballot_sync(~0u, flag != 0);
    __shared__ int wcnt[24];
    __shared__ int wpre[25];
    if (lane == 0) wcnt[warp] = __popc(bal);
    __syncthreads();
    if (tid == 0) {
        int acc = 0;
        #pragma unroll
        for (int w = 0; w < 24; w++) { wpre[w] = acc; acc += wcnt[w]; }
        wpre[24] = acc;
        g_colcnt[j] = acc;
    }
    __syncthreads();
    if (flag) {
        int pos = wpre[warp] + __popc(bal & ((1u << lane) - 1u));
        g_colrows[j * NN + pos] = tid;
    }
}

// ---------------- kernel 3: exclusive scan of colcnt (768, one block) ----------------
__global__ void scan_kernel() {
    __shared__ int tmp[NN];
    int t = threadIdx.x;
    int my = g_colcnt[t];
    tmp[t] = my;
    __syncthreads();
    for (int o = 1; o < NN; o <<= 1) {
        int v = (t >= o) ? tmp[t - o] : 0;
        __syncthreads();
        tmp[t] += v;
        __syncthreads();
    }
    g_colstart[t] = tmp[t] - my;
    if (t == NN - 1) g_totE = tmp[t];
}

// ---------------- kernel 4: flatten padded column lists ----------------
__global__ void flatten_kernel() {
    int j = blockIdx.x;
    int st = g_colstart[j];
    int c  = g_colcnt[j];
    for (int e = threadIdx.x; e < c; e += blockDim.x) {
        g_ei[st + e] = g_colrows[j * NN + e];
        g_ej[st + e] = j;
    }
}

// ---------------- kernel 5: per-node precompute A, Base ----------------
constexpr int RPB = 8;
__global__ void precompute_kernel(const float* __restrict__ xext, int use_g,
                                  const float* __restrict__ W1,
                                  const float* __restrict__ b1) {
    const float* xp = use_g ? g_x1 : xext;
    __shared__ float sx[RPB][NU];
    int R0 = blockIdx.x * RPB;
    int tid = threadIdx.x;          // 0..159
    for (int idx = tid; idx < RPB * NU; idx += 160)
        sx[idx >> 6][idx & 63] = xp[(size_t)R0 * NU + idx];
    __syncthreads();
    int n = tid;
    float a[RPB], bs[RPB];
    #pragma unroll
    for (int r = 0; r < RPB; r++) { a[r] = 0.0f; bs[r] = 0.0f; }
    if (n < NIN) {
        #pragma unroll 4
        for (int u = 0; u < NU; u++) {
            float wa = W1[u * NIN + n];
            float wb = W1[(NU + u) * NIN + n];
            #pragma unroll
            for (int r = 0; r < RPB; r++) {
                a[r]  = fmaf(sx[r][u], wa, a[r]);
                bs[r] = fmaf(sx[r][u], wb, bs[r]);
            }
        }
        float bb = b1[n];
        #pragma unroll
        for (int r = 0; r < RPB; r++) {
            g_A   [(size_t)(R0 + r) * NPD + n] = a[r];
            g_Base[(size_t)(R0 + r) * NPD + n] = bs[r] + bb;
        }
    } else {
        #pragma unroll
        for (int r = 0; r < RPB; r++) {
            g_A   [(size_t)(R0 + r) * NPD + n] = 0.0f;
            g_Base[(size_t)(R0 + r) * NPD + n] = 0.0f;
        }
    }
}

// ---------------- kernel 6: flat edge phase (2 edges x 2 batches per warp-iter) ----------------
__global__ void __launch_bounds__(256, 3) edge_kernel(
    const float* __restrict__ rel,
    const float* __restrict__ W1,      // (136,136); rows 128..135 = rel weights
    const float* __restrict__ w2,      // (136,1)
    const float* __restrict__ b2p)     // (1,)
{
    __shared__ float sW1c[NK * NPD];

    int tid = threadIdx.x, warp = tid >> 5, lane = tid & 31;

    for (int idx = tid; idx < NK * NPD; idx += 256) {
        int kk = idx / NPD, n = idx % NPD;
        sW1c[idx] = (n < NIN) ? W1[(2 * NU + kk) * NIN + n] : 0.0f;
    }
    float w2l[5];
    #pragma unroll
    for (int m = 0; m < 5; m++) {
        int n = lane + 32 * m;
        w2l[m] = (n < NIN) ? w2[n] : 0.0f;
    }
    float b2 = __ldg(b2p);
    __syncthreads();

    int totE = g_totE;
    int nPairs = (totE + 1) >> 1;
    int gw = blockIdx.x * 8 + warp;
    int nw = gridDim.x * 8;

    for (int P = gw; P < nPairs; P += nw) {
        int e0 = P << 1;
        int  ev[2];
        bool valid[2];
        int  iv[2];
        float rv[2][8];
        float h[4][5];      // chain c = s*2 + b

        #pragma unroll
        for (int s = 0; s < 2; s++) {
            int e = e0 + s;
            valid[s] = (e < totE);
            if (!valid[s]) e = totE - 1;
            ev[s] = e;
            int i = g_ei[e];
            int j = g_ej[e];
            iv[s] = i;
            const float4* rp = reinterpret_cast<const float4*>(
                rel + ((size_t)i * NN + j) * NK);
            float4 r0 = rp[0], r1 = rp[1];
            rv[s][0] = r0.x; rv[s][1] = r0.y; rv[s][2] = r0.z; rv[s][3] = r0.w;
            rv[s][4] = r1.x; rv[s][5] = r1.y; rv[s][6] = r1.z; rv[s][7] = r1.w;
            #pragma unroll
            for (int b = 0; b < 2; b++) {
                const float* Ar = g_A    + ((size_t)(b * NN + i)) * NPD;
                const float* Br = g_Base + ((size_t)(b * NN + j)) * NPD;
                #pragma unroll
                for (int m = 0; m < 5; m++)
                    h[s * 2 + b][m] = Ar[lane + 32 * m] + Br[lane + 32 * m];
            }
        }

        // rel-term MLP: per k-step, 5 LDS serve 20 FMAs
        #pragma unroll
        for (int kk = 0; kk < NK; kk++) {
            float w1v[5];
            #pragma unroll
            for (int m = 0; m < 5; m++)
                w1v[m] = sW1c[kk * NPD + lane + 32 * m];
            #pragma unroll
            for (int c = 0; c < 4; c++)
                #pragma unroll
                for (int m = 0; m < 5; m++)
                    h[c][m] = fmaf(rv[c >> 1][kk], w1v[m], h[c][m]);
        }

        // leaky + dot with w2 (4 independent chains)
        float d[4];
        #pragma unroll
        for (int c = 0; c < 4; c++) {
            float acc = 0.0f;
            #pragma unroll
            for (int m = 0; m < 5; m++) {
                float hv = h[c][m];
                hv = fmaxf(hv, SLOPE * hv);
                acc = fmaf(hv, w2l[m], acc);
            }
            d[c] = acc;
        }
        // interleaved butterflies (4 independent chains)
        #pragma unroll
        for (int o = 16; o > 0; o >>= 1) {
            #pragma unroll
            for (int c = 0; c < 4; c++)
                d[c] += __shfl_xor_sync(~0u, d[c], o);
        }
        // chain c = s*2 + b ; lane c stores its chain's value
        #pragma unroll
        for (int c = 0; c < 4; c++) {
            int s = c >> 1, b = c & 1;
            float o2 = d[c] + b2;
            o2 = fmaxf(o2, SLOPE * o2);
            float val = o2 * g_invD[iv[s]];
            if (lane == c && valid[s])
                g_edgeval[b * MAXE + ev[s]] = val;
        }
    }
}

// ---------------- kernel 7: deterministic column reduce + output scale ----------------
__global__ void reduce_scale_kernel(const float* __restrict__ xin_ext,
                                    float* __restrict__ xout_ext,
                                    int use_g_in, int use_g_out) {
    const float* xin  = use_g_in  ? g_x1 : xin_ext;
    float*       xout = use_g_out ? g_x1 : xout_ext;
    int gw = blockIdx.x * (blockDim.x >> 5) + (threadIdx.x >> 5);
    if (gw >= NB * NN) return;
    int lane = threadIdx.x & 31;
    int b = gw / NN, j = gw % NN;
    int st = g_colstart[j], c = g_colcnt[j];
    const float* ev = g_edgeval + (size_t)b * MAXE + st;
    float s = 0.0f;
    for (int e = lane; e < c; e += 32) s += ev[e];
    #pragma unroll
    for (int o = 16; o > 0; o >>= 1) s += __shfl_xor_sync(~0u, s, o);
    size_t base = (size_t)gw * NU;
    xout[base + lane]      = xin[base + lane]      * s;
    xout[base + 32 + lane] = xin[base + 32 + lane] * s;
}

// ---------------- launch ----------------
extern "C" void kernel_launch(void* const* d_in, const int* in_sizes, int n_in,
                              void* d_out, int out_size) {
    const float* seq  = (const float*)d_in[0];
    const float* rel  = (const float*)d_in[1];
    const float* w1_1 = (const float*)d_in[2];
    const float* b1_1 = (const float*)d_in[3];
    const float* w1_2 = (const float*)d_in[4];
    const float* b1_2 = (const float*)d_in[5];
    const float* w2_1 = (const float*)d_in[6];
    const float* b2_1 = (const float*)d_in[7];
    const float* w2_2 = (const float*)d_in[8];
    const float* b2_2 = (const float*)d_in[9];
    float* out = (float*)d_out;

    maskdeg_kernel   <<<NN, 256>>>(rel);
    build_cols_kernel<<<NN, 768>>>();
    scan_kernel      <<<1, NN>>>();
    flatten_kernel   <<<NN, 256>>>();

    const int EGRID = 444;   // 3 blocks/SM, one wave at launch_bounds(256,3)
    const int RGRID = (NB * NN + 7) / 8;

    // hop 1: seq -> g_x1
    precompute_kernel  <<<NB * NN / RPB, 160>>>(seq, 0, w1_1, b1_1);
    edge_kernel        <<<EGRID, 256>>>(rel, w1_1, w1_2, b1_2);
    reduce_scale_kernel<<<RGRID, 256>>>(seq, nullptr, 0, 1);

    // hop 2: g_x1 -> out
    precompute_kernel  <<<NB * NN / RPB, 160>>>(nullptr, 1, w2_1, b2_1);
    edge_kernel        <<<EGRID, 256>>>(rel, w2_1, w2_2, b2_2);
    reduce_scale_kernel<<<RGRID, 256>>>(nullptr, out, 1, 0);
}